// round 2
// baseline (speedup 1.0000x reference)
#include <cuda_runtime.h>
#include <float.h>
#include <stdint.h>

// ===========================================================================
// TopK SAE pipeline (fp32, CUDA-core baseline — round 1: capture-safe topk)
//   latents = x @ W_enc^T + b_enc        [8192, 12288]
//   (vals, idx) = top32(latents, axis=1)
//   sparse = scatter(vals at idx)        [8192, 12288]
//   recon  = sparse @ W_dec^T + b_dec    [8192, 768]  (k-sparse gather form)
// Output layout: d_out = [recon (8192*768) | sparse (8192*12288)] fp32
// ===========================================================================

#define N_ROWS 8192
#define DM     768
#define DS     12288
#define KSEL   32

// Scratch (device globals — no allocation allowed)
__device__ float g_latents[(size_t)N_ROWS * DS];   // 402.7 MB
__device__ float g_wdecT[(size_t)DS * DM];         // 37.7 MB  (W_dec transposed)
__device__ float g_vals[N_ROWS * KSEL];
__device__ int   g_idx [N_ROWS * KSEL];

// ---------------------------------------------------------------------------
// packed f32x2 helpers (sm_100+ only; doubles fp32 FMA throughput)
// ---------------------------------------------------------------------------
__device__ __forceinline__ unsigned long long pack2(float lo, float hi) {
    unsigned long long p;
    asm("mov.b64 %0, {%1, %2};" : "=l"(p) : "f"(lo), "f"(hi));
    return p;
}
__device__ __forceinline__ void unpack2(unsigned long long p, float& lo, float& hi) {
    asm("mov.b64 {%0, %1}, %2;" : "=f"(lo), "=f"(hi) : "l"(p));
}
__device__ __forceinline__ unsigned long long fma2(unsigned long long a,
                                                   unsigned long long b,
                                                   unsigned long long c) {
    unsigned long long d;
    asm("fma.rn.f32x2 %0, %1, %2, %3;" : "=l"(d) : "l"(a), "l"(b), "l"(c));
    return d;
}

// ---------------------------------------------------------------------------
// Kernel 1: encode GEMM  C[m,s] = sum_k x[m,k] * W_enc[s,k] + b_enc[s]
// NT-gemm, BM=BN=128, BK=16, 256 threads, 8x8 microtile via f32x2
// ---------------------------------------------------------------------------
#define BM 128
#define BN 128
#define BK 16
#define SPAD 4   // smem row padding (floats)

__global__ __launch_bounds__(256, 2)
void encode_gemm_kernel(const float* __restrict__ x,
                        const float* __restrict__ W,
                        const float* __restrict__ b_enc)
{
    __shared__ float As[BK][BM + SPAD];
    __shared__ float Bs[BK][BN + SPAD];

    const int tid = threadIdx.x;
    const int m0  = blockIdx.y * BM;
    const int s0  = blockIdx.x * BN;
    const int tx  = tid & 15;    // column microtile id (0..15)
    const int ty  = tid >> 4;    // row    microtile id (0..15)

    unsigned long long acc[8][4];
    #pragma unroll
    for (int i = 0; i < 8; i++)
        #pragma unroll
        for (int j = 0; j < 4; j++)
            acc[i][j] = 0ULL;   // (0.0f, 0.0f)

    for (int kt = 0; kt < DM; kt += BK) {
        // load A and B tiles: 128 rows x 16 k each, as float4, transpose to [k][row]
        #pragma unroll
        for (int t = 0; t < 2; t++) {
            int idx = tid + t * 256;       // 0..511
            int row = idx >> 2;            // 0..127
            int kg  = idx & 3;             // 0..3 (group of 4 k)
            float4 va = *(const float4*)&x[(size_t)(m0 + row) * DM + kt + kg * 4];
            As[kg * 4 + 0][row] = va.x;
            As[kg * 4 + 1][row] = va.y;
            As[kg * 4 + 2][row] = va.z;
            As[kg * 4 + 3][row] = va.w;
            float4 vb = *(const float4*)&W[(size_t)(s0 + row) * DM + kt + kg * 4];
            Bs[kg * 4 + 0][row] = vb.x;
            Bs[kg * 4 + 1][row] = vb.y;
            Bs[kg * 4 + 2][row] = vb.z;
            Bs[kg * 4 + 3][row] = vb.w;
        }
        __syncthreads();

        #pragma unroll
        for (int kk = 0; kk < BK; kk++) {
            float4 a0 = *(const float4*)&As[kk][ty * 4];
            float4 a1 = *(const float4*)&As[kk][64 + ty * 4];
            float4 b0 = *(const float4*)&Bs[kk][tx * 4];
            float4 b1 = *(const float4*)&Bs[kk][64 + tx * 4];
            unsigned long long bp[4];
            bp[0] = pack2(b0.x, b0.y);
            bp[1] = pack2(b0.z, b0.w);
            bp[2] = pack2(b1.x, b1.y);
            bp[3] = pack2(b1.z, b1.w);
            float av[8] = {a0.x, a0.y, a0.z, a0.w, a1.x, a1.y, a1.z, a1.w};
            #pragma unroll
            for (int i = 0; i < 8; i++) {
                unsigned long long ap = pack2(av[i], av[i]);
                #pragma unroll
                for (int j = 0; j < 4; j++)
                    acc[i][j] = fma2(ap, bp[j], acc[i][j]);
            }
        }
        __syncthreads();
    }

    // epilogue: add b_enc, store fp32 latents
    const int c0 = s0 + tx * 4;
    const int c1 = s0 + 64 + tx * 4;
    float4 be0 = *(const float4*)&b_enc[c0];
    float4 be1 = *(const float4*)&b_enc[c1];
    #pragma unroll
    for (int i = 0; i < 8; i++) {
        int r = m0 + ((i < 4) ? (ty * 4 + i) : (64 + ty * 4 + (i - 4)));
        float f0, f1, f2, f3;
        unpack2(acc[i][0], f0, f1);
        unpack2(acc[i][1], f2, f3);
        float4 out0 = make_float4(f0 + be0.x, f1 + be0.y, f2 + be0.z, f3 + be0.w);
        *(float4*)&g_latents[(size_t)r * DS + c0] = out0;
        unpack2(acc[i][2], f0, f1);
        unpack2(acc[i][3], f2, f3);
        float4 out1 = make_float4(f0 + be1.x, f1 + be1.y, f2 + be1.z, f3 + be1.w);
        *(float4*)&g_latents[(size_t)r * DS + c1] = out1;
    }
}

// ---------------------------------------------------------------------------
// Kernel 2: per-row top-32 — register-resident row, incremental argmax.
// One CTA (256 threads) per row. Each thread owns 48 elements
// (col = tid + 256*j). Per iteration: warp+block argmax of cached per-thread
// maxima; only the winning thread clears its element and rescans its 48.
// Static smem: 72 bytes. No dynamic smem (round-0 capture failure was the
// 48KB+static over-limit launch).
// ---------------------------------------------------------------------------
#define TPR 48   // elements per thread = DS / 256

__global__ __launch_bounds__(256)
void topk_kernel()
{
    __shared__ float swv[8];
    __shared__ int   swi[8];
    __shared__ int   s_bi;

    const int row = blockIdx.x;
    const int tid = threadIdx.x;
    const float* lat = g_latents + (size_t)row * DS;

    float v[TPR];
    #pragma unroll
    for (int j = 0; j < TPR; j++)
        v[j] = lat[tid + j * 256];

    // initial per-thread argmax
    float lmax = -FLT_MAX;
    int   lj   = 0;
    #pragma unroll
    for (int j = 0; j < TPR; j++)
        if (v[j] > lmax) { lmax = v[j]; lj = j; }

    for (int it = 0; it < KSEL; it++) {
        // warp argmax of (lmax, global col)
        float wv = lmax;
        int   wg = lj * 256 + tid;
        #pragma unroll
        for (int off = 16; off > 0; off >>= 1) {
            float ov = __shfl_down_sync(0xffffffffu, wv, off);
            int   og = __shfl_down_sync(0xffffffffu, wg, off);
            if (ov > wv) { wv = ov; wg = og; }
        }
        if ((tid & 31) == 0) {
            swv[tid >> 5] = wv;
            swi[tid >> 5] = wg;
        }
        __syncthreads();
        if (tid == 0) {
            float bv = swv[0]; int bg = swi[0];
            #pragma unroll
            for (int w = 1; w < 8; w++)
                if (swv[w] > bv) { bv = swv[w]; bg = swi[w]; }
            g_vals[row * KSEL + it] = bv;
            g_idx [row * KSEL + it] = bg;
            s_bi = bg;
        }
        __syncthreads();
        const int bg = s_bi;
        if ((bg & 255) == tid) {
            const int jw = bg >> 8;
            #pragma unroll
            for (int j = 0; j < TPR; j++)
                if (j == jw) v[j] = -FLT_MAX;
            lmax = -FLT_MAX; lj = 0;
            #pragma unroll
            for (int j = 0; j < TPR; j++)
                if (v[j] > lmax) { lmax = v[j]; lj = j; }
        }
        __syncthreads();
    }
}

// ---------------------------------------------------------------------------
// Kernel 3a: zero-fill sparse output region
// ---------------------------------------------------------------------------
__global__ void zero_kernel(float4* __restrict__ p, size_t n4)
{
    size_t i = (size_t)blockIdx.x * blockDim.x + threadIdx.x;
    if (i < n4) p[i] = make_float4(0.f, 0.f, 0.f, 0.f);
}

// ---------------------------------------------------------------------------
// Kernel 3b: scatter top-k values into sparse
// ---------------------------------------------------------------------------
__global__ void scatter_kernel(float* __restrict__ sparse)
{
    int row = blockIdx.x;
    int j   = threadIdx.x;   // 0..31
    sparse[(size_t)row * DS + g_idx[row * KSEL + j]] = g_vals[row * KSEL + j];
}

// ---------------------------------------------------------------------------
// Kernel 4: transpose W_dec [768, 12288] -> W_decT [12288, 768]
// ---------------------------------------------------------------------------
__global__ void transpose_kernel(const float* __restrict__ W_dec)
{
    __shared__ float t[32][33];
    int s0 = blockIdx.x * 32;
    int d0 = blockIdx.y * 32;
    for (int i = threadIdx.y; i < 32; i += 8)
        t[i][threadIdx.x] = W_dec[(size_t)(d0 + i) * DS + s0 + threadIdx.x];
    __syncthreads();
    for (int i = threadIdx.y; i < 32; i += 8)
        g_wdecT[(size_t)(s0 + i) * DM + d0 + threadIdx.x] = t[threadIdx.x][i];
}

// ---------------------------------------------------------------------------
// Kernel 5: decode — recon[n,d] = b_dec[d] + sum_j vals[j] * W_decT[idx[j], d]
// one CTA per row, 256 threads, 3 d per thread (768 = 3*256), coalesced gathers
// ---------------------------------------------------------------------------
__global__ __launch_bounds__(256)
void decode_kernel(const float* __restrict__ b_dec, float* __restrict__ recon)
{
    __shared__ float sv[KSEL];
    __shared__ int   si[KSEL];
    const int row = blockIdx.x;
    if (threadIdx.x < KSEL) {
        sv[threadIdx.x] = g_vals[row * KSEL + threadIdx.x];
        si[threadIdx.x] = g_idx [row * KSEL + threadIdx.x];
    }
    __syncthreads();

    const int d = threadIdx.x;
    float a0 = 0.f, a1 = 0.f, a2 = 0.f;
    #pragma unroll 4
    for (int j = 0; j < KSEL; j++) {
        const float* wr = g_wdecT + (size_t)si[j] * DM;
        float v = sv[j];
        a0 += v * wr[d];
        a1 += v * wr[d + 256];
        a2 += v * wr[d + 512];
    }
    float* out = recon + (size_t)row * DM;
    out[d]       = a0 + b_dec[d];
    out[d + 256] = a1 + b_dec[d + 256];
    out[d + 512] = a2 + b_dec[d + 512];
}

// ---------------------------------------------------------------------------
// launch
// ---------------------------------------------------------------------------
extern "C" void kernel_launch(void* const* d_in, const int* in_sizes, int n_in,
                              void* d_out, int out_size)
{
    const float* x     = (const float*)d_in[0];
    const float* W_enc = (const float*)d_in[1];
    const float* b_enc = (const float*)d_in[2];
    const float* W_dec = (const float*)d_in[3];
    const float* b_dec = (const float*)d_in[4];
    // d_in[5] = k (fixed at 32, compiled in)

    float* recon  = (float*)d_out;
    float* sparse = recon + (size_t)N_ROWS * DM;

    // independent: transpose W_dec (needed by decode only)
    transpose_kernel<<<dim3(DS / 32, DM / 32), dim3(32, 8)>>>(W_dec);

    // encode: latents = x @ W_enc^T + b_enc
    encode_gemm_kernel<<<dim3(DS / BN, N_ROWS / BM), 256>>>(x, W_enc, b_enc);

    // per-row top-32
    topk_kernel<<<N_ROWS, 256>>>();

    // sparse = zeros; scatter
    size_t n4 = (size_t)N_ROWS * DS / 4;
    zero_kernel<<<(unsigned)((n4 + 255) / 256), 256>>>((float4*)sparse, n4);
    scatter_kernel<<<N_ROWS, KSEL>>>(sparse);

    // recon
    decode_kernel<<<N_ROWS, 256>>>(b_dec, recon);
}

// round 3
// speedup vs baseline: 2.5054x; 2.5054x over previous
#include <cuda_runtime.h>
#include <cuda_bf16.h>
#include <float.h>
#include <stdint.h>

// ===========================================================================
// TopK SAE — round 2: bf16 tensor-core encode + exact fp32 refine
//   approx latents = bf16(x) @ bf16(W_enc)^T + b_enc     (mma.sync, fp32 acc)
//   cand48 = top48(approx latents)  per row
//   exact  = fp32 dot(x, W_enc[cand]) + b_enc[cand]      (refine)
//   (vals, idx) = top32(exact among cand48)
//   sparse = scatter; recon = k-sparse decode
// Output layout: d_out = [recon (8192*768) | sparse (8192*12288)] fp32
// ===========================================================================

#define N_ROWS 8192
#define DM     768
#define DS     12288
#define KSEL   32
#define NCAND  48

// Scratch (device globals — no allocation allowed)
__device__ float          g_latents[(size_t)N_ROWS * DS];  // 402.7 MB approx scores
__device__ __nv_bfloat16  g_xb[(size_t)N_ROWS * DM];       // bf16 x
__device__ __nv_bfloat16  g_wb[(size_t)DS * DM];           // bf16 W_enc
__device__ float          g_wdecT[(size_t)DS * DM];        // W_dec transposed
__device__ float          g_cval[N_ROWS * NCAND];
__device__ int            g_cidx[N_ROWS * NCAND];
__device__ float          g_vals[N_ROWS * KSEL];
__device__ int            g_idx [N_ROWS * KSEL];

// ---------------------------------------------------------------------------
// Kernel 0: fp32 -> bf16 conversion (vectorized)
// ---------------------------------------------------------------------------
__global__ void convert_kernel(const float* __restrict__ src,
                               __nv_bfloat16* __restrict__ dst, int n)
{
    int i = (blockIdx.x * blockDim.x + threadIdx.x) * 4;
    if (i < n) {
        float4 v = *(const float4*)(src + i);
        *(__nv_bfloat162*)(dst + i)     = __floats2bfloat162_rn(v.x, v.y);
        *(__nv_bfloat162*)(dst + i + 2) = __floats2bfloat162_rn(v.z, v.w);
    }
}

// ---------------------------------------------------------------------------
// Kernel 1: bf16 NT-GEMM (tensor cores): scores[m,s] = x[m,:] . W_enc[s,:] + b
// CTA tile 128x128x32, 8 warps (4x2), warp tile 32x64, mma.sync m16n8k16,
// cp.async double-buffered smem, swizzled for conflict-free ldmatrix.
// ---------------------------------------------------------------------------
#define MT 128
#define NT 128
#define KT 32
#define KITERS (DM / KT)   // 24

__device__ __forceinline__ uint32_t smem_u32(const void* p) {
    return (uint32_t)__cvta_generic_to_shared(p);
}
// byte offset in a [128 rows x 32 bf16] tile: row stride 64B, 16B chunks,
// chunk swizzled so ldmatrix's 8-row phases hit all 8 chunk positions.
__device__ __forceinline__ int swz(int row, int kchunk) {
    return row * 64 + ((kchunk ^ ((row >> 1) & 3)) * 16);
}

__device__ __forceinline__ void ldsm_x4(uint32_t& r0, uint32_t& r1,
                                        uint32_t& r2, uint32_t& r3, uint32_t addr) {
    asm volatile("ldmatrix.sync.aligned.m8n8.x4.shared.b16 {%0,%1,%2,%3}, [%4];"
                 : "=r"(r0), "=r"(r1), "=r"(r2), "=r"(r3) : "r"(addr));
}

__global__ __launch_bounds__(256, 2)
void encode_gemm_bf16(const float* __restrict__ b_enc)
{
    __shared__ __align__(16) char As[2][128 * 64];
    __shared__ __align__(16) char Bs[2][128 * 64];

    const int tid  = threadIdx.x;
    const int wid  = tid >> 5;
    const int lane = tid & 31;
    const int m0   = blockIdx.y * MT;
    const int n0   = blockIdx.x * NT;
    const int wm   = (wid & 3) * 32;   // warp m offset within tile
    const int wn   = (wid >> 2) * 64;  // warp n offset within tile

    float acc[2][8][4];
    #pragma unroll
    for (int mt = 0; mt < 2; mt++)
        #pragma unroll
        for (int nt = 0; nt < 8; nt++)
            #pragma unroll
            for (int f = 0; f < 4; f++)
                acc[mt][nt][f] = 0.f;

    // cp.async issue of one k-chunk into stage st
    auto issue = [&](int st, int kt) {
        #pragma unroll
        for (int i = 0; i < 2; i++) {
            int c   = tid + i * 256;      // 0..511 chunk id
            int row = c >> 2;
            int kc  = c & 3;
            const __nv_bfloat16* ga = g_xb + (size_t)(m0 + row) * DM + kt + kc * 8;
            uint32_t da = smem_u32(As[st] + swz(row, kc));
            asm volatile("cp.async.cg.shared.global [%0], [%1], 16;\n" :: "r"(da), "l"(ga));
            const __nv_bfloat16* gb = g_wb + (size_t)(n0 + row) * DM + kt + kc * 8;
            uint32_t db = smem_u32(Bs[st] + swz(row, kc));
            asm volatile("cp.async.cg.shared.global [%0], [%1], 16;\n" :: "r"(db), "l"(gb));
        }
        asm volatile("cp.async.commit_group;\n");
    };

    issue(0, 0);

    for (int it = 0; it < KITERS; it++) {
        if (it + 1 < KITERS) {
            issue((it + 1) & 1, (it + 1) * KT);
            asm volatile("cp.async.wait_group 1;\n");
        } else {
            asm volatile("cp.async.wait_group 0;\n");
        }
        __syncthreads();

        const char* A = As[it & 1];
        const char* B = Bs[it & 1];
        #pragma unroll
        for (int ks = 0; ks < 2; ks++) {          // two k16 steps per chunk
            const int kb = ks * 2;                // base 16B-chunk for this k16
            uint32_t a[2][4];
            #pragma unroll
            for (int mt = 0; mt < 2; mt++) {
                int row = wm + mt * 16 + (lane & 15);
                int kc  = kb + (lane >> 4);
                ldsm_x4(a[mt][0], a[mt][1], a[mt][2], a[mt][3],
                        smem_u32(A + swz(row, kc)));
            }
            uint32_t b[8][2];
            #pragma unroll
            for (int ng = 0; ng < 4; ng++) {      // n16 groups (2 n-tiles each)
                int row = wn + ng * 16 + (lane & 15);
                int kc  = kb + (lane >> 4);
                uint32_t r0, r1, r2, r3;
                ldsm_x4(r0, r1, r2, r3, smem_u32(B + swz(row, kc)));
                b[ng * 2][0]     = r0;   // n-tile even, k0..7
                b[ng * 2 + 1][0] = r1;   // n-tile odd,  k0..7
                b[ng * 2][1]     = r2;   // n-tile even, k8..15
                b[ng * 2 + 1][1] = r3;   // n-tile odd,  k8..15
            }
            #pragma unroll
            for (int mt = 0; mt < 2; mt++)
                #pragma unroll
                for (int nt = 0; nt < 8; nt++)
                    asm volatile(
                        "mma.sync.aligned.m16n8k16.row.col.f32.bf16.bf16.f32 "
                        "{%0,%1,%2,%3}, {%4,%5,%6,%7}, {%8,%9}, {%0,%1,%2,%3};"
                        : "+f"(acc[mt][nt][0]), "+f"(acc[mt][nt][1]),
                          "+f"(acc[mt][nt][2]), "+f"(acc[mt][nt][3])
                        : "r"(a[mt][0]), "r"(a[mt][1]), "r"(a[mt][2]), "r"(a[mt][3]),
                          "r"(b[nt][0]), "r"(b[nt][1]));
        }
        __syncthreads();
    }

    // epilogue: + b_enc, coalesced float2 stores
    #pragma unroll
    for (int mt = 0; mt < 2; mt++) {
        int r0 = m0 + wm + mt * 16 + (lane >> 2);
        #pragma unroll
        for (int nt = 0; nt < 8; nt++) {
            int cg = n0 + wn + nt * 8 + (lane & 3) * 2;
            float2 be = *(const float2*)&b_enc[cg];
            float2 o0 = make_float2(acc[mt][nt][0] + be.x, acc[mt][nt][1] + be.y);
            float2 o1 = make_float2(acc[mt][nt][2] + be.x, acc[mt][nt][3] + be.y);
            *(float2*)&g_latents[(size_t)r0 * DS + cg]       = o0;
            *(float2*)&g_latents[(size_t)(r0 + 8) * DS + cg] = o1;
        }
    }
}

// ---------------------------------------------------------------------------
// Kernel 2: per-row top-48 candidates from approx scores (register-resident)
// ---------------------------------------------------------------------------
#define TPR 48   // elements per thread = DS / 256

__global__ __launch_bounds__(256)
void topk_cand_kernel()
{
    __shared__ float swv[8];
    __shared__ int   swi[8];
    __shared__ int   s_bi;

    const int row = blockIdx.x;
    const int tid = threadIdx.x;
    const float* lat = g_latents + (size_t)row * DS;

    float v[TPR];
    #pragma unroll
    for (int j = 0; j < TPR; j++)
        v[j] = lat[tid + j * 256];

    float lmax = -FLT_MAX;
    int   lj   = 0;
    #pragma unroll
    for (int j = 0; j < TPR; j++)
        if (v[j] > lmax) { lmax = v[j]; lj = j; }

    for (int it = 0; it < NCAND; it++) {
        float wv = lmax;
        int   wg = lj * 256 + tid;
        #pragma unroll
        for (int off = 16; off > 0; off >>= 1) {
            float ov = __shfl_down_sync(0xffffffffu, wv, off);
            int   og = __shfl_down_sync(0xffffffffu, wg, off);
            if (ov > wv) { wv = ov; wg = og; }
        }
        if ((tid & 31) == 0) { swv[tid >> 5] = wv; swi[tid >> 5] = wg; }
        __syncthreads();
        if (tid == 0) {
            float bv = swv[0]; int bg = swi[0];
            #pragma unroll
            for (int w = 1; w < 8; w++)
                if (swv[w] > bv) { bv = swv[w]; bg = swi[w]; }
            g_cidx[row * NCAND + it] = bg;
            s_bi = bg;
        }
        __syncthreads();
        const int bg = s_bi;
        if ((bg & 255) == tid) {
            const int jw = bg >> 8;
            #pragma unroll
            for (int j = 0; j < TPR; j++)
                if (j == jw) v[j] = -FLT_MAX;
            lmax = -FLT_MAX; lj = 0;
            #pragma unroll
            for (int j = 0; j < TPR; j++)
                if (v[j] > lmax) { lmax = v[j]; lj = j; }
        }
        __syncthreads();
    }
}

// ---------------------------------------------------------------------------
// Kernel 3: exact fp32 refine — recompute 48 candidate dots, pick exact top-32
// one CTA (256 thr, 8 warps) per row; x row in smem; W_enc rows from L2.
// ---------------------------------------------------------------------------
__global__ __launch_bounds__(256)
void refine_kernel(const float* __restrict__ x,
                   const float* __restrict__ W_enc,
                   const float* __restrict__ b_enc)
{
    __shared__ float xr[DM];
    __shared__ float cv[NCAND];
    __shared__ int   ci[NCAND];

    const int row  = blockIdx.x;
    const int tid  = threadIdx.x;
    const int wid  = tid >> 5;
    const int lane = tid & 31;

    for (int d = tid; d < DM; d += 256)
        xr[d] = x[(size_t)row * DM + d];
    if (tid < NCAND)
        ci[tid] = g_cidx[row * NCAND + tid];
    __syncthreads();

    for (int j = wid; j < NCAND; j += 8) {
        const int idx = ci[j];
        const float* wr = W_enc + (size_t)idx * DM;
        float s = 0.f;
        #pragma unroll
        for (int d = lane; d < DM; d += 32)
            s += xr[d] * wr[d];
        #pragma unroll
        for (int off = 16; off > 0; off >>= 1)
            s += __shfl_down_sync(0xffffffffu, s, off);
        if (lane == 0) cv[j] = s + b_enc[idx];
    }
    __syncthreads();

    // warp 0: exact top-32 among 48
    if (wid == 0) {
        float v0 = cv[lane];
        float v1 = (lane < NCAND - 32) ? cv[lane + 32] : -FLT_MAX;
        const int i0 = lane, i1 = lane + 32;
        for (int it = 0; it < KSEL; it++) {
            float m = v0; int mi = i0;
            if (v1 > m) { m = v1; mi = i1; }
            float wv = m; int wg = mi;
            #pragma unroll
            for (int off = 16; off > 0; off >>= 1) {
                float ov = __shfl_down_sync(0xffffffffu, wv, off);
                int   og = __shfl_down_sync(0xffffffffu, wg, off);
                if (ov > wv) { wv = ov; wg = og; }
            }
            wv = __shfl_sync(0xffffffffu, wv, 0);
            wg = __shfl_sync(0xffffffffu, wg, 0);
            if (lane == 0) {
                g_vals[row * KSEL + it] = wv;
                g_idx [row * KSEL + it] = ci[wg];
            }
            if (i0 == wg) v0 = -FLT_MAX;
            if (i1 == wg) v1 = -FLT_MAX;
        }
    }
}

// ---------------------------------------------------------------------------
// Kernel 4a/4b: zero-fill + scatter sparse
// ---------------------------------------------------------------------------
__global__ void zero_kernel(float4* __restrict__ p, size_t n4)
{
    size_t i = (size_t)blockIdx.x * blockDim.x + threadIdx.x;
    if (i < n4) p[i] = make_float4(0.f, 0.f, 0.f, 0.f);
}

__global__ void scatter_kernel(float* __restrict__ sparse)
{
    int row = blockIdx.x;
    int j   = threadIdx.x;   // 0..31
    sparse[(size_t)row * DS + g_idx[row * KSEL + j]] = g_vals[row * KSEL + j];
}

// ---------------------------------------------------------------------------
// Kernel 5: transpose W_dec [768, 12288] -> [12288, 768]
// ---------------------------------------------------------------------------
__global__ void transpose_kernel(const float* __restrict__ W_dec)
{
    __shared__ float t[32][33];
    int s0 = blockIdx.x * 32;
    int d0 = blockIdx.y * 32;
    for (int i = threadIdx.y; i < 32; i += 8)
        t[i][threadIdx.x] = W_dec[(size_t)(d0 + i) * DS + s0 + threadIdx.x];
    __syncthreads();
    for (int i = threadIdx.y; i < 32; i += 8)
        g_wdecT[(size_t)(s0 + i) * DM + d0 + threadIdx.x] = t[threadIdx.x][i];
}

// ---------------------------------------------------------------------------
// Kernel 6: decode — recon[n,d] = b_dec[d] + sum_j vals[j] * W_decT[idx[j], d]
// ---------------------------------------------------------------------------
__global__ __launch_bounds__(256)
void decode_kernel(const float* __restrict__ b_dec, float* __restrict__ recon)
{
    __shared__ float sv[KSEL];
    __shared__ int   si[KSEL];
    const int row = blockIdx.x;
    if (threadIdx.x < KSEL) {
        sv[threadIdx.x] = g_vals[row * KSEL + threadIdx.x];
        si[threadIdx.x] = g_idx [row * KSEL + threadIdx.x];
    }
    __syncthreads();

    const int d = threadIdx.x;
    float a0 = 0.f, a1 = 0.f, a2 = 0.f;
    #pragma unroll 4
    for (int j = 0; j < KSEL; j++) {
        const float* wr = g_wdecT + (size_t)si[j] * DM;
        float v = sv[j];
        a0 += v * wr[d];
        a1 += v * wr[d + 256];
        a2 += v * wr[d + 512];
    }
    float* out = recon + (size_t)row * DM;
    out[d]       = a0 + b_dec[d];
    out[d + 256] = a1 + b_dec[d + 256];
    out[d + 512] = a2 + b_dec[d + 512];
}

// ---------------------------------------------------------------------------
// launch
// ---------------------------------------------------------------------------
extern "C" void kernel_launch(void* const* d_in, const int* in_sizes, int n_in,
                              void* d_out, int out_size)
{
    const float* x     = (const float*)d_in[0];
    const float* W_enc = (const float*)d_in[1];
    const float* b_enc = (const float*)d_in[2];
    const float* W_dec = (const float*)d_in[3];
    const float* b_dec = (const float*)d_in[4];

    float* recon  = (float*)d_out;
    float* sparse = recon + (size_t)N_ROWS * DM;

    // bf16 conversions for tensor-core encode
    {
        __nv_bfloat16* xb; cudaGetSymbolAddress((void**)&xb, g_xb);
        __nv_bfloat16* wb; cudaGetSymbolAddress((void**)&wb, g_wb);
        int nx = N_ROWS * DM;
        int nw = DS * DM;
        convert_kernel<<<(nx / 4 + 255) / 256, 256>>>(x, xb, nx);
        convert_kernel<<<(nw / 4 + 255) / 256, 256>>>(W_enc, wb, nw);
    }

    // independent: W_dec transpose for decode
    transpose_kernel<<<dim3(DS / 32, DM / 32), dim3(32, 8)>>>(W_dec);

    // approx encode on tensor cores
    encode_gemm_bf16<<<dim3(DS / NT, N_ROWS / MT), 256>>>(b_enc);

    // top-48 candidates per row
    topk_cand_kernel<<<N_ROWS, 256>>>();

    // exact fp32 refine -> top-32 vals/idx
    refine_kernel<<<N_ROWS, 256>>>(x, W_enc, b_enc);

    // sparse = zeros; scatter
    size_t n4 = (size_t)N_ROWS * DS / 4;
    zero_kernel<<<(unsigned)((n4 + 255) / 256), 256>>>((float4*)sparse, n4);
    scatter_kernel<<<N_ROWS, KSEL>>>(sparse);

    // recon
    decode_kernel<<<N_ROWS, 256>>>(b_dec, recon);
}